// round 2
// baseline (speedup 1.0000x reference)
#include <cuda_runtime.h>
#include <cfloat>
#include <cstdint>

#define N_NODES 50000
#define IN_DIM  1024
#define E_EDGES 100000
#define NUM_REL 40
#define HEADS   4
#define OUT_DIM 200
#define HID     800
#define BATCH   8192
#define NEG_SLOPE 0.2f

// ---------------- scratch (device globals; no allocation allowed) ----------------
__device__ __align__(16) float g_h  [(size_t)N_NODES * HID];   // node_emb @ W
__device__ __align__(16) float g_out[(size_t)N_NODES * HID];   // aggregated output
__device__ float g_ssrc  [N_NODES * HEADS];
__device__ float g_sdst  [N_NODES * HEADS];
__device__ float g_rlog  [NUM_REL * HEADS];
__device__ float g_segmax[N_NODES * HEADS];
__device__ float g_denom [N_NODES * HEADS];
__device__ float g_elog  [E_EDGES * HEADS];
__device__ int   g_is64;   // 1 if index arrays are int64, 0 if int32

// ---------------- helpers ----------------
__device__ __forceinline__ int load_idx(const void* p, int i) {
    if (g_is64) return (int)((const long long*)p)[i];
    return ((const int*)p)[i];
}

__device__ __forceinline__ void atomicMaxFloat(float* addr, float val) {
    if (val >= 0.0f) atomicMax((int*)addr, __float_as_int(val));
    else             atomicMin((unsigned int*)addr, __float_as_uint(val));
}

__device__ __forceinline__ float warp_reduce(float v) {
    #pragma unroll
    for (int o = 16; o > 0; o >>= 1) v += __shfl_down_sync(0xffffffffu, v, o);
    return v;
}

// ---------------- 0) dtype detection ----------------
// If the first 64 entries interpreted as int64 all land in [0, N_NODES), the
// data is int64. For int32 data, each interpreted value is lo + hi*2^32 where
// hi is a neighboring random index in [0,50000) — at least one is out of range
// with probability ~1.
__global__ void detect_dtype_kernel(const void* edge_index) {
    if (threadIdx.x == 0 && blockIdx.x == 0) {
        const long long* p = (const long long*)edge_index;
        int ok = 1;
        for (int i = 0; i < 64; i++) {
            long long v = p[i];
            if (v < 0 || v >= N_NODES) { ok = 0; break; }
        }
        g_is64 = ok;
    }
}

// ---------------- 1) GEMM: g_h = node_emb[50000,1024] @ W[1024,800] ----------------
// BM=128, BN=64, BK=16, 256 threads, each computes 8x4.
__global__ void __launch_bounds__(256) gemm_kernel(const float* __restrict__ A,
                                                   const float* __restrict__ Wm) {
    const int t  = threadIdx.x;
    const int tx = t & 15;          // 0..15 -> 4 cols each
    const int ty = t >> 4;          // 0..15 -> 8 rows each
    const int row0 = blockIdx.x * 128;
    const int col0 = blockIdx.y * 64;

    __shared__ float As[16][128];
    __shared__ float Bs[16][64];

    float acc[8][4];
    #pragma unroll
    for (int i = 0; i < 8; i++)
        #pragma unroll
        for (int j = 0; j < 4; j++) acc[i][j] = 0.0f;

    for (int k0 = 0; k0 < IN_DIM; k0 += 16) {
        // load A tile: 128 rows x 16 k = 512 float4 slots
        #pragma unroll
        for (int i = 0; i < 2; i++) {
            int s  = t + 256 * i;        // 0..511
            int r  = s >> 2;             // row within tile
            int kq = (s & 3) * 4;        // k-offset (0,4,8,12)
            float4 v = make_float4(0.f, 0.f, 0.f, 0.f);
            int gr = row0 + r;
            if (gr < N_NODES)
                v = *(const float4*)(A + (size_t)gr * IN_DIM + k0 + kq);
            As[kq + 0][r] = v.x; As[kq + 1][r] = v.y;
            As[kq + 2][r] = v.z; As[kq + 3][r] = v.w;
        }
        // load B tile: 16 k x 64 cols = 256 float4 slots
        {
            int kr = t >> 4;             // 0..15
            int cq = (t & 15) * 4;       // 0..60
            float4 v = make_float4(0.f, 0.f, 0.f, 0.f);
            int gc = col0 + cq;
            if (gc < HID)
                v = *(const float4*)(Wm + (size_t)(k0 + kr) * HID + gc);
            Bs[kr][cq + 0] = v.x; Bs[kr][cq + 1] = v.y;
            Bs[kr][cq + 2] = v.z; Bs[kr][cq + 3] = v.w;
        }
        __syncthreads();

        #pragma unroll
        for (int kk = 0; kk < 16; kk++) {
            float a[8], b[4];
            #pragma unroll
            for (int i = 0; i < 8; i++) a[i] = As[kk][ty * 8 + i];
            #pragma unroll
            for (int j = 0; j < 4; j++) b[j] = Bs[kk][tx * 4 + j];
            #pragma unroll
            for (int i = 0; i < 8; i++)
                #pragma unroll
                for (int j = 0; j < 4; j++) acc[i][j] = fmaf(a[i], b[j], acc[i][j]);
        }
        __syncthreads();
    }

    const int gc = col0 + tx * 4;
    if (gc < HID) {
        #pragma unroll
        for (int i = 0; i < 8; i++) {
            int gr = row0 + ty * 8 + i;
            if (gr < N_NODES) {
                float4 v = make_float4(acc[i][0], acc[i][1], acc[i][2], acc[i][3]);
                *(float4*)(g_h + (size_t)gr * HID + gc) = v;
            }
        }
    }
}

// ---------------- 2) init: out=0, segmax=-inf, denom=0 ----------------
__global__ void init_kernel() {
    const size_t tid = (size_t)blockIdx.x * blockDim.x + threadIdx.x;
    const size_t nthreads = (size_t)gridDim.x * blockDim.x;
    float4* o4 = (float4*)g_out;
    const size_t tot4 = (size_t)N_NODES * HID / 4;
    for (size_t i = tid; i < tot4; i += nthreads)
        o4[i] = make_float4(0.f, 0.f, 0.f, 0.f);
    if (tid < (size_t)N_NODES * HEADS) {
        g_segmax[tid] = -FLT_MAX;
        g_denom[tid]  = 0.0f;
    }
}

// ---------------- 3) per-node attention projections ----------------
__global__ void node_logits_kernel(const float* __restrict__ a_src,
                                   const float* __restrict__ a_dst) {
    int wid  = (blockIdx.x * blockDim.x + threadIdx.x) >> 5;
    int lane = threadIdx.x & 31;
    if (wid >= N_NODES * HEADS) return;
    int n = wid >> 2, h = wid & 3;
    const float* hp = g_h + (size_t)n * HID + h * OUT_DIM;
    const float* as = a_src + h * OUT_DIM;
    const float* ad = a_dst + h * OUT_DIM;
    float ss = 0.f, sd = 0.f;
    for (int d = lane; d < OUT_DIM; d += 32) {
        float v = hp[d];
        ss = fmaf(v, as[d], ss);
        sd = fmaf(v, ad[d], sd);
    }
    ss = warp_reduce(ss);
    sd = warp_reduce(sd);
    if (lane == 0) { g_ssrc[wid] = ss; g_sdst[wid] = sd; }
}

__global__ void rel_logits_kernel(const float* __restrict__ rel_feat,
                                  const float* __restrict__ a_rel) {
    int wid  = (blockIdx.x * blockDim.x + threadIdx.x) >> 5;
    int lane = threadIdx.x & 31;
    if (wid >= NUM_REL * HEADS) return;
    int r = wid >> 2, h = wid & 3;
    const float* rp = rel_feat + (size_t)r * HID + h * OUT_DIM;
    const float* ar = a_rel + h * OUT_DIM;
    float s = 0.f;
    for (int d = lane; d < OUT_DIM; d += 32) s = fmaf(rp[d], ar[d], s);
    s = warp_reduce(s);
    if (lane == 0) g_rlog[wid] = s;
}

// ---------------- 4) per-edge logits + segment max ----------------
__global__ void edge_max_kernel(const void* __restrict__ ei,
                                const void* __restrict__ et) {
    int idx = blockIdx.x * blockDim.x + threadIdx.x;
    if (idx >= E_EDGES * HEADS) return;
    int e = idx >> 2, h = idx & 3;
    int s = load_idx(ei, e);
    int d = load_idx(ei, E_EDGES + e);
    int r = load_idx(et, e);
    float x = g_ssrc[s * 4 + h] + g_sdst[d * 4 + h] + g_rlog[r * 4 + h];
    x = (x >= 0.f) ? x : NEG_SLOPE * x;
    g_elog[idx] = x;
    atomicMaxFloat(&g_segmax[d * 4 + h], x);
}

// ---------------- 5) exp + segment sum ----------------
__global__ void edge_exp_kernel(const void* __restrict__ ei) {
    int idx = blockIdx.x * blockDim.x + threadIdx.x;
    if (idx >= E_EDGES * HEADS) return;
    int e = idx >> 2, h = idx & 3;
    int d = load_idx(ei, E_EDGES + e);
    float ev = expf(g_elog[idx] - g_segmax[d * 4 + h]);
    g_elog[idx] = ev;
    atomicAdd(&g_denom[d * 4 + h], ev);
}

// ---------------- 6) weighted scatter-aggregate: out[dst] += alpha * h[src] --------
__global__ void edge_agg_kernel(const void* __restrict__ ei) {
    int wid  = (blockIdx.x * blockDim.x + threadIdx.x) >> 5;
    int lane = threadIdx.x & 31;
    if (wid >= E_EDGES) return;
    int s = load_idx(ei, wid);
    int d = load_idx(ei, E_EDGES + wid);
    float alpha[HEADS];
    #pragma unroll
    for (int h = 0; h < HEADS; h++)
        alpha[h] = g_elog[wid * 4 + h] / g_denom[d * 4 + h];
    const float4* hs = (const float4*)(g_h + (size_t)s * HID);
    float4*       op = (float4*)(g_out + (size_t)d * HID);
    for (int c = lane; c < HID / 4; c += 32) {   // 200 float4 chunks; head = c/50
        float a = alpha[c / 50];
        float4 v = hs[c];
        float4 w = make_float4(v.x * a, v.y * a, v.z * a, v.w * a);
        atomicAdd(op + c, w);                    // vector RED, sm_90+
    }
}

// ---------------- 7) DistMult scoring ----------------
__global__ void distmult_kernel(const float* __restrict__ bias,
                                const float* __restrict__ rel_emb,
                                const void* __restrict__ si,
                                const void* __restrict__ ri,
                                const void* __restrict__ di,
                                float* __restrict__ out) {
    int wid  = (blockIdx.x * blockDim.x + threadIdx.x) >> 5;
    int lane = threadIdx.x & 31;
    if (wid >= BATCH) return;
    int s = load_idx(si, wid);
    int r = load_idx(ri, wid);
    int d = load_idx(di, wid);
    const float* ps = g_out + (size_t)s * HID;
    const float* pd = g_out + (size_t)d * HID;
    const float* pr = rel_emb + (size_t)r * HID;
    float acc = 0.f;
    for (int k = lane; k < HID; k += 32) {
        float b = bias[k];
        acc = fmaf((ps[k] + b) * pr[k], (pd[k] + b), acc);
    }
    acc = warp_reduce(acc);
    if (lane == 0) out[wid] = acc;
}

// ---------------- launch ----------------
extern "C" void kernel_launch(void* const* d_in, const int* in_sizes, int n_in,
                              void* d_out, int out_size) {
    const float* node_emb   = (const float*)d_in[0];
    const float* Wm         = (const float*)d_in[1];
    const float* bias       = (const float*)d_in[2];
    const float* a_src      = (const float*)d_in[3];
    const float* a_dst      = (const float*)d_in[4];
    const float* a_rel      = (const float*)d_in[5];
    const float* rel_feat   = (const float*)d_in[6];
    const float* rel_emb    = (const float*)d_in[7];
    const void*  edge_index = d_in[8];
    const void*  edge_type  = d_in[9];
    const void*  src_ids    = d_in[10];
    const void*  rel_ids    = d_in[11];
    const void*  dst_ids    = d_in[12];
    float* out = (float*)d_out;

    detect_dtype_kernel<<<1, 32>>>(edge_index);

    dim3 gemm_grid((N_NODES + 127) / 128, (HID + 63) / 64);
    gemm_kernel<<<gemm_grid, 256>>>(node_emb, Wm);

    init_kernel<<<(N_NODES * HEADS + 255) / 256, 256>>>();

    node_logits_kernel<<<(N_NODES * HEADS * 32 + 255) / 256, 256>>>(a_src, a_dst);
    rel_logits_kernel<<<(NUM_REL * HEADS * 32 + 255) / 256, 256>>>(rel_feat, a_rel);

    edge_max_kernel<<<(E_EDGES * HEADS + 255) / 256, 256>>>(edge_index, edge_type);
    edge_exp_kernel<<<(E_EDGES * HEADS + 255) / 256, 256>>>(edge_index);
    edge_agg_kernel<<<(E_EDGES * 32 + 255) / 256, 256>>>(edge_index);

    distmult_kernel<<<(BATCH * 32 + 255) / 256, 256>>>(bias, rel_emb,
                                                       src_ids, rel_ids, dst_ids, out);
}